// round 3
// baseline (speedup 1.0000x reference)
#include <cuda_runtime.h>

// ---------------------------------------------------------------------------
// QuantumDecoder: z -> tanh(z@W_in) -> 4-qubit circuit Z-expectations ->
//                 relu(@W1) -> sigmoid(@W2)
//
// The post-RY circuit (RX/RY/RZ with fixed theta + CX ring, 2 layers) is a
// fixed 16x16 unitary M. With real product state s0 from the RY layer:
//   z_q = s0^T * Re(M^H Z_q M) * s0      (real symmetric quadratic form)
// A setup kernel simulates the 16 basis columns and builds the 4 matrices.
//
// R3 restructure: 2048 blocks x 128 threads, 32 rows/block, 4 threads/row.
//  - stage-1 dot split over 4 threads + shfl butterfly reduce
//  - each thread computes one quadratic form (its q = lane%4), shfl exchange
//  - final GEMM: thread c owns cols {16j+4c..+3}; 64B-contiguous broadcast
//    LDS of W2, 64B-contiguous-per-row warp stores.
// ---------------------------------------------------------------------------

__device__ float g_A[4 * 16 * 16];   // Re(M^H Z_q M), q = 0..3

// ---- packed f32x2 helpers (Blackwell) -------------------------------------
__device__ __forceinline__ unsigned long long pack2(float x, float y) {
    unsigned long long r;
    asm("mov.b64 %0, {%1, %2};" : "=l"(r) : "f"(x), "f"(y));
    return r;
}
__device__ __forceinline__ void unpack2(unsigned long long v, float& x, float& y) {
    asm("mov.b64 {%0, %1}, %2;" : "=f"(x), "=f"(y) : "l"(v));
}
__device__ __forceinline__ unsigned long long ffma2(unsigned long long a,
                                                    unsigned long long b,
                                                    unsigned long long c) {
    unsigned long long d;
    asm("fma.rn.f32x2 %0, %1, %2, %3;" : "=l"(d) : "l"(a), "l"(b), "l"(c));
    return d;
}
__device__ __forceinline__ float sigmoidf_fast(float x) {
    float e = __expf(-x);                 // MUFU.EX2 path
    return __fdividef(1.0f, 1.0f + e);    // MUFU.RCP path
}

// ---------------------------------------------------------------------------
// Setup kernel: simulate the fixed part of the circuit on the 16 basis
// states, then build A_q = Re(M^H Z_q M).  Runs once per launch, trivial cost.
// ---------------------------------------------------------------------------
__global__ void qd_setup_kernel(const float* __restrict__ theta) {
    __shared__ float2 M[16][16];   // M[x][j] = <x| circuit |j>
    int tid = threadIdx.x;

    if (tid < 16) {
        float2 st[16];
        for (int x = 0; x < 16; x++) st[x] = make_float2(0.f, 0.f);
        st[tid] = make_float2(1.f, 0.f);

        for (int layer = 0; layer < 2; layer++) {
            for (int q = 0; q < 4; q++) {
                float th = theta[layer * 4 + q];
                float ch = cosf(0.5f * th), sh = sinf(0.5f * th);
                int bit = 1 << q;
                for (int a = 0; a < 8; a++) {
                    int i0 = ((a >> q) << (q + 1)) | (a & (bit - 1));
                    int i1 = i0 | bit;
                    float2 x0 = st[i0], x1 = st[i1];
                    // Rx = [[c, -i s], [-i s, c]]
                    float2 y0 = make_float2(ch * x0.x + sh * x1.y, ch * x0.y - sh * x1.x);
                    float2 y1 = make_float2(ch * x1.x + sh * x0.y, ch * x1.y - sh * x0.x);
                    // Ry = [[c, -s], [s, c]]
                    float2 z0 = make_float2(ch * y0.x - sh * y1.x, ch * y0.y - sh * y1.y);
                    float2 z1 = make_float2(sh * y0.x + ch * y1.x, sh * y0.y + ch * y1.y);
                    // Rz = diag(c - i s, c + i s)
                    st[i0] = make_float2(ch * z0.x + sh * z0.y, ch * z0.y - sh * z0.x);
                    st[i1] = make_float2(ch * z1.x - sh * z1.y, ch * z1.y + sh * z1.x);
                }
            }
            // CX ring: (c,t) = (0,1),(1,2),(2,3),(3,0)
            const int cs[4] = {0, 1, 2, 3};
            const int ts[4] = {1, 2, 3, 0};
            for (int g = 0; g < 4; g++) {
                float2 tmp[16];
                int c = cs[g], t = ts[g];
                for (int m = 0; m < 16; m++) tmp[m] = st[m ^ (((m >> c) & 1) << t)];
                for (int m = 0; m < 16; m++) st[m] = tmp[m];
            }
        }
        for (int x = 0; x < 16; x++) M[x][tid] = st[x];
    }
    __syncthreads();

    for (int idx = tid; idx < 1024; idx += blockDim.x) {
        int q = idx >> 8, i = (idx >> 4) & 15, j = idx & 15;
        float s = 0.f;
        for (int x = 0; x < 16; x++) {
            float2 mi = M[x][i], mj = M[x][j];
            float d = mi.x * mj.x + mi.y * mj.y;   // Re(conj(M[x,i]) * M[x,j])
            s += ((x >> q) & 1) ? -d : d;
        }
        g_A[idx] = s;
    }
}

// ---------------------------------------------------------------------------
// Main kernel: 32 rows per block, 4 threads per row.
// ---------------------------------------------------------------------------
__global__ void __launch_bounds__(128, 6) qd_main_kernel(
    const float* __restrict__ z,   const float* __restrict__ W_in,
    const float* __restrict__ b_in, const float* __restrict__ W1,
    const float* __restrict__ b1,  const float* __restrict__ W2,
    const float* __restrict__ b2,  float* __restrict__ out)
{
    __shared__ float4 sWin[128];        // W_in [128][4]
    __shared__ float  sA[1024];         // A_q matrices
    __shared__ float  sW1[32];          // W1 [4][8]
    __shared__ float  sb1[8];
    __shared__ float  sbin[4];
    __shared__ float4 sW2[8 * 196];     // W2 [8][784] as float4
    __shared__ float4 sb2[196];

    int tid = threadIdx.x;
    sWin[tid] = ((const float4*)W_in)[tid];
    for (int i = tid; i < 1024; i += 128) sA[i] = g_A[i];
    if (tid < 32) sW1[tid] = W1[tid];
    if (tid < 8)  sb1[tid] = b1[tid];
    if (tid < 4)  sbin[tid] = b_in[tid];
    for (int i = tid; i < 8 * 196; i += 128) sW2[i] = ((const float4*)W2)[i];
    for (int i = tid; i < 196; i += 128) sb2[i] = ((const float4*)b2)[i];
    __syncthreads();

    const int rl = tid >> 2;        // local row 0..31
    const int c  = tid & 3;         // sub-thread 0..3 (also: owned qubit)
    const int row = blockIdx.x * 32 + rl;

    // ---- 1) partial dot: k in [c*32, c*32+32) over 4 output cols ----------
    const float4* zp = (const float4*)(z + (size_t)row * 128);
    float ax = 0.f, ay = 0.f, az = 0.f, aw = 0.f;
#pragma unroll
    for (int i = 0; i < 8; i++) {
        float4 zv = zp[c * 8 + i];
        int k0 = c * 32 + i * 4;
        float4 wa = sWin[k0], wb = sWin[k0 + 1], wc4 = sWin[k0 + 2], wd = sWin[k0 + 3];
        ax = fmaf(zv.x, wa.x, ax); ay = fmaf(zv.x, wa.y, ay);
        az = fmaf(zv.x, wa.z, az); aw = fmaf(zv.x, wa.w, aw);
        ax = fmaf(zv.y, wb.x, ax); ay = fmaf(zv.y, wb.y, ay);
        az = fmaf(zv.y, wb.z, az); aw = fmaf(zv.y, wb.w, aw);
        ax = fmaf(zv.z, wc4.x, ax); ay = fmaf(zv.z, wc4.y, ay);
        az = fmaf(zv.z, wc4.z, az); aw = fmaf(zv.z, wc4.w, aw);
        ax = fmaf(zv.w, wd.x, ax); ay = fmaf(zv.w, wd.y, ay);
        az = fmaf(zv.w, wd.z, az); aw = fmaf(zv.w, wd.w, aw);
    }
    // butterfly reduce within each group of 4 lanes (bits 0,1 of lane)
    ax += __shfl_xor_sync(0xffffffffu, ax, 1);
    ay += __shfl_xor_sync(0xffffffffu, ay, 1);
    az += __shfl_xor_sync(0xffffffffu, az, 1);
    aw += __shfl_xor_sync(0xffffffffu, aw, 1);
    ax += __shfl_xor_sync(0xffffffffu, ax, 2);
    ay += __shfl_xor_sync(0xffffffffu, ay, 2);
    az += __shfl_xor_sync(0xffffffffu, az, 2);
    aw += __shfl_xor_sync(0xffffffffu, aw, 2);

    float a0 = tanhf(ax + sbin[0]);
    float a1 = tanhf(ay + sbin[1]);
    float a2 = tanhf(az + sbin[2]);
    float a3 = tanhf(aw + sbin[3]);

    // ---- 2) s0: real RY product state -------------------------------------
    float c0, s0s, c1, s1s, c2, s2s, c3, s3s;
    __sincosf(0.5f * a0, &s0s, &c0);
    __sincosf(0.5f * a1, &s1s, &c1);
    __sincosf(0.5f * a2, &s2s, &c2);
    __sincosf(0.5f * a3, &s3s, &c3);
    float u0 = c0 * c1, u1 = s0s * c1, u2 = c0 * s1s, u3 = s0s * s1s;
    float v0 = c2 * c3, v1 = s2s * c3, v2 = c2 * s3s, v3 = s2s * s3s;
    float st[16];
    st[0]  = u0 * v0; st[1]  = u1 * v0; st[2]  = u2 * v0; st[3]  = u3 * v0;
    st[4]  = u0 * v1; st[5]  = u1 * v1; st[6]  = u2 * v1; st[7]  = u3 * v1;
    st[8]  = u0 * v2; st[9]  = u1 * v2; st[10] = u2 * v2; st[11] = u3 * v2;
    st[12] = u0 * v3; st[13] = u1 * v3; st[14] = u2 * v3; st[15] = u3 * v3;

    // ---- 3) this thread computes z_q for q = c only -----------------------
    const float* Aq = &sA[c * 256];
    float zqm = 0.f;
#pragma unroll
    for (int i = 0; i < 16; i++) {
        float wi = 0.f;
#pragma unroll
        for (int j = 0; j < 16; j++)
            wi = fmaf(Aq[i * 16 + j], st[j], wi);
        zqm = fmaf(st[i], wi, zqm);
    }
    // exchange the 4 z_q within the group of 4 lanes
    int base = tid & ~3;
    float zq0 = __shfl_sync(0xffffffffu, zqm, base + 0);
    float zq1 = __shfl_sync(0xffffffffu, zqm, base + 1);
    float zq2 = __shfl_sync(0xffffffffu, zqm, base + 2);
    float zq3 = __shfl_sync(0xffffffffu, zqm, base + 3);

    // ---- 4) h = relu(qexp @ W1 + b1);  qexp[k] = zq[3-k] ------------------
    unsigned long long h2[8];
#pragma unroll
    for (int m = 0; m < 8; m++) {
        float t = sb1[m];
        t = fmaf(zq3, sW1[0 * 8 + m], t);
        t = fmaf(zq2, sW1[1 * 8 + m], t);
        t = fmaf(zq1, sW1[2 * 8 + m], t);
        t = fmaf(zq0, sW1[3 * 8 + m], t);
        t = fmaxf(t, 0.f);
        h2[m] = pack2(t, t);
    }

    // ---- 5) out = sigmoid(h @ W2 + b2): thread c owns cols {16j+4c..+3} ---
    float4* op = (float4*)(out + (size_t)row * 784);
    const ulonglong2* W2p = (const ulonglong2*)sW2;
    const ulonglong2* b2p = (const ulonglong2*)sb2;
#pragma unroll 2
    for (int j = 0; j < 49; j++) {
        int cg = j * 4 + c;                       // float4 column-group index
        ulonglong2 bb = b2p[cg];
        unsigned long long acc0 = bb.x, acc1 = bb.y;
#pragma unroll
        for (int k = 0; k < 8; k++) {
            ulonglong2 w = W2p[k * 196 + cg];
            acc0 = ffma2(h2[k], w.x, acc0);
            acc1 = ffma2(h2[k], w.y, acc1);
        }
        float f0, f1, f2, f3;
        unpack2(acc0, f0, f1);
        unpack2(acc1, f2, f3);
        op[cg] = make_float4(sigmoidf_fast(f0), sigmoidf_fast(f1),
                             sigmoidf_fast(f2), sigmoidf_fast(f3));
    }
}

// ---------------------------------------------------------------------------
extern "C" void kernel_launch(void* const* d_in, const int* in_sizes, int n_in,
                              void* d_out, int out_size) {
    const float* z     = (const float*)d_in[0];
    const float* W_in  = (const float*)d_in[1];
    const float* b_in  = (const float*)d_in[2];
    const float* theta = (const float*)d_in[3];
    const float* W1    = (const float*)d_in[4];
    const float* b1    = (const float*)d_in[5];
    const float* W2    = (const float*)d_in[6];
    const float* b2    = (const float*)d_in[7];

    int B = in_sizes[0] / 128;          // 65536
    qd_setup_kernel<<<1, 128>>>(theta);
    qd_main_kernel<<<B / 32, 128>>>(z, W_in, b_in, W1, b1, W2, b2, (float*)d_out);
}

// round 4
// speedup vs baseline: 1.3891x; 1.3891x over previous
#include <cuda_runtime.h>

// ---------------------------------------------------------------------------
// QuantumDecoder: z -> tanh(z@W_in) -> 4-qubit circuit Z-expectations ->
//                 relu(@W1) -> sigmoid(@W2)
//
// The post-RY circuit (RX/RY/RZ with fixed theta + CX ring, 2 layers) is a
// fixed 16x16 unitary M. With real product state s0 from the RY layer:
//   z_q = s0^T * Re(M^H Z_q M) * s0      (real symmetric quadratic form)
// Symmetric pair form: z_q = sum_{i<=j} S_q[i,j] * s_i * s_j with
// S_q[i,j] = (i==j ? 1 : 2) * A_q[i,j].
//
// R4: two-kernel split. Front-end (per-row) writes h (relu layer output,
// pre-duplicated f32x2) to a device-global scratch; GEMM kernel keeps W2
// entirely in registers (thread owns 4 output columns), reads h via uniform
// broadcast LDG, writes coalesced float4 stores. No LDS in the hot loop.
// ---------------------------------------------------------------------------

__device__ float g_S[136 * 4];                         // symmetric pair coeffs
__device__ unsigned long long g_h2[65536 * 8];         // h duplicated as f32x2

// ---- packed f32x2 helpers (Blackwell) -------------------------------------
__device__ __forceinline__ unsigned long long pack2(float x, float y) {
    unsigned long long r;
    asm("mov.b64 %0, {%1, %2};" : "=l"(r) : "f"(x), "f"(y));
    return r;
}
__device__ __forceinline__ void unpack2(unsigned long long v, float& x, float& y) {
    asm("mov.b64 {%0, %1}, %2;" : "=f"(x), "=f"(y) : "l"(v));
}
__device__ __forceinline__ unsigned long long ffma2(unsigned long long a,
                                                    unsigned long long b,
                                                    unsigned long long c) {
    unsigned long long d;
    asm("fma.rn.f32x2 %0, %1, %2, %3;" : "=l"(d) : "l"(a), "l"(b), "l"(c));
    return d;
}
__device__ __forceinline__ float sigmoidf_fast(float x) {
    float e = __expf(-x);                 // MUFU.EX2 path
    return __fdividef(1.0f, 1.0f + e);    // MUFU.RCP path
}

// ---------------------------------------------------------------------------
// Setup kernel: simulate fixed circuit on 16 basis states, build
// A_q = Re(M^H Z_q M), then the symmetric pair table S.
// ---------------------------------------------------------------------------
__global__ void qd_setup_kernel(const float* __restrict__ theta) {
    __shared__ float2 M[16][16];   // M[x][j] = <x| circuit |j>
    __shared__ float  Atmp[1024];
    int tid = threadIdx.x;

    if (tid < 16) {
        float2 st[16];
        for (int x = 0; x < 16; x++) st[x] = make_float2(0.f, 0.f);
        st[tid] = make_float2(1.f, 0.f);

        for (int layer = 0; layer < 2; layer++) {
            for (int q = 0; q < 4; q++) {
                float th = theta[layer * 4 + q];
                float ch = cosf(0.5f * th), sh = sinf(0.5f * th);
                int bit = 1 << q;
                for (int a = 0; a < 8; a++) {
                    int i0 = ((a >> q) << (q + 1)) | (a & (bit - 1));
                    int i1 = i0 | bit;
                    float2 x0 = st[i0], x1 = st[i1];
                    // Rx = [[c, -i s], [-i s, c]]
                    float2 y0 = make_float2(ch * x0.x + sh * x1.y, ch * x0.y - sh * x1.x);
                    float2 y1 = make_float2(ch * x1.x + sh * x0.y, ch * x1.y - sh * x0.x);
                    // Ry = [[c, -s], [s, c]]
                    float2 z0 = make_float2(ch * y0.x - sh * y1.x, ch * y0.y - sh * y1.y);
                    float2 z1 = make_float2(sh * y0.x + ch * y1.x, sh * y0.y + ch * y1.y);
                    // Rz = diag(c - i s, c + i s)
                    st[i0] = make_float2(ch * z0.x + sh * z0.y, ch * z0.y - sh * z0.x);
                    st[i1] = make_float2(ch * z1.x - sh * z1.y, ch * z1.y + sh * z1.x);
                }
            }
            // CX ring: (c,t) = (0,1),(1,2),(2,3),(3,0)
            const int cs[4] = {0, 1, 2, 3};
            const int ts[4] = {1, 2, 3, 0};
            for (int g = 0; g < 4; g++) {
                float2 tmp[16];
                int c = cs[g], t = ts[g];
                for (int m = 0; m < 16; m++) tmp[m] = st[m ^ (((m >> c) & 1) << t)];
                for (int m = 0; m < 16; m++) st[m] = tmp[m];
            }
        }
        for (int x = 0; x < 16; x++) M[x][tid] = st[x];
    }
    __syncthreads();

    for (int idx = tid; idx < 1024; idx += blockDim.x) {
        int q = idx >> 8, i = (idx >> 4) & 15, j = idx & 15;
        float s = 0.f;
        for (int x = 0; x < 16; x++) {
            float2 mi = M[x][i], mj = M[x][j];
            float d = mi.x * mj.x + mi.y * mj.y;   // Re(conj(M[x,i]) * M[x,j])
            s += ((x >> q) & 1) ? -d : d;
        }
        Atmp[idx] = s;
    }
    __syncthreads();

    // pair table: pair p -> (i, j>=i); S[p][q] = (i==j?1:2)*A_q[i][j]
    for (int e = tid; e < 544; e += blockDim.x) {
        int pair = e >> 2, q = e & 3;
        int i = 0, rem = pair;
        while (rem >= 16 - i) { rem -= 16 - i; i++; }
        int j = i + rem;
        g_S[pair * 4 + q] = (i == j ? 1.f : 2.f) * Atmp[q * 256 + i * 16 + j];
    }
}

// ---------------------------------------------------------------------------
// Kernel A: front-end, one thread per row. Writes duplicated-h to g_h2.
// ---------------------------------------------------------------------------
__global__ void __launch_bounds__(256) qd_front_kernel(
    const float* __restrict__ z,   const float* __restrict__ W_in,
    const float* __restrict__ b_in, const float* __restrict__ W1,
    const float* __restrict__ b1)
{
    __shared__ float4 sWin[128];        // W_in [128][4]
    __shared__ float4 sS[136];          // symmetric pair coeffs (4 q's each)
    __shared__ float  sW1[32];          // W1 [4][8]
    __shared__ float  sb1[8];
    __shared__ float  sbin[4];

    int tid = threadIdx.x;
    if (tid < 128) sWin[tid] = ((const float4*)W_in)[tid];
    if (tid < 136) sS[tid] = ((const float4*)g_S)[tid];
    if (tid < 32)  sW1[tid] = W1[tid];
    if (tid < 8)   sb1[tid] = b1[tid];
    if (tid < 4)   sbin[tid] = b_in[tid];
    __syncthreads();

    int r = blockIdx.x * 256 + tid;

    // ---- 1) lat = tanh(z_row @ W_in + b_in) -------------------------------
    const float4* zp = (const float4*)(z + (size_t)r * 128);
    float ax = sbin[0], ay = sbin[1], az = sbin[2], aw = sbin[3];
#pragma unroll 8
    for (int k = 0; k < 32; k++) {
        float4 zv = zp[k];
        float4 wa = sWin[4 * k + 0], wb = sWin[4 * k + 1];
        float4 wc = sWin[4 * k + 2], wd = sWin[4 * k + 3];
        ax = fmaf(zv.x, wa.x, ax); ay = fmaf(zv.x, wa.y, ay);
        az = fmaf(zv.x, wa.z, az); aw = fmaf(zv.x, wa.w, aw);
        ax = fmaf(zv.y, wb.x, ax); ay = fmaf(zv.y, wb.y, ay);
        az = fmaf(zv.y, wb.z, az); aw = fmaf(zv.y, wb.w, aw);
        ax = fmaf(zv.z, wc.x, ax); ay = fmaf(zv.z, wc.y, ay);
        az = fmaf(zv.z, wc.z, az); aw = fmaf(zv.z, wc.w, aw);
        ax = fmaf(zv.w, wd.x, ax); ay = fmaf(zv.w, wd.y, ay);
        az = fmaf(zv.w, wd.z, az); aw = fmaf(zv.w, wd.w, aw);
    }
    float a0 = tanhf(ax), a1 = tanhf(ay), a2 = tanhf(az), a3 = tanhf(aw);

    // ---- 2) s0: real RY product state -------------------------------------
    float c0, s0s, c1, s1s, c2, s2s, c3, s3s;
    __sincosf(0.5f * a0, &s0s, &c0);
    __sincosf(0.5f * a1, &s1s, &c1);
    __sincosf(0.5f * a2, &s2s, &c2);
    __sincosf(0.5f * a3, &s3s, &c3);
    float u0 = c0 * c1, u1 = s0s * c1, u2 = c0 * s1s, u3 = s0s * s1s;
    float v0 = c2 * c3, v1 = s2s * c3, v2 = c2 * s3s, v3 = s2s * s3s;
    float st[16];
    st[0]  = u0 * v0; st[1]  = u1 * v0; st[2]  = u2 * v0; st[3]  = u3 * v0;
    st[4]  = u0 * v1; st[5]  = u1 * v1; st[6]  = u2 * v1; st[7]  = u3 * v1;
    st[8]  = u0 * v2; st[9]  = u1 * v2; st[10] = u2 * v2; st[11] = u3 * v2;
    st[12] = u0 * v3; st[13] = u1 * v3; st[14] = u2 * v3; st[15] = u3 * v3;

    // ---- 3) all 4 quadratic forms via symmetric pair table ----------------
    float zq0 = 0.f, zq1 = 0.f, zq2 = 0.f, zq3 = 0.f;
    {
        int pidx = 0;
#pragma unroll
        for (int i = 0; i < 16; i++) {
            float si = st[i];
#pragma unroll
            for (int j = i; j < 16; j++) {
                float p = si * st[j];
                float4 cv = sS[pidx++];
                zq0 = fmaf(p, cv.x, zq0);
                zq1 = fmaf(p, cv.y, zq1);
                zq2 = fmaf(p, cv.z, zq2);
                zq3 = fmaf(p, cv.w, zq3);
            }
        }
    }

    // ---- 4) h = relu(qexp @ W1 + b1);  qexp[k] = zq[3-k]; store dup'd -----
    unsigned long long hh[8];
#pragma unroll
    for (int m = 0; m < 8; m++) {
        float t = sb1[m];
        t = fmaf(zq3, sW1[0 * 8 + m], t);
        t = fmaf(zq2, sW1[1 * 8 + m], t);
        t = fmaf(zq1, sW1[2 * 8 + m], t);
        t = fmaf(zq0, sW1[3 * 8 + m], t);
        t = fmaxf(t, 0.f);
        hh[m] = pack2(t, t);
    }
    ulonglong2* hp = (ulonglong2*)(g_h2 + (size_t)r * 8);
    hp[0] = make_ulonglong2(hh[0], hh[1]);
    hp[1] = make_ulonglong2(hh[2], hh[3]);
    hp[2] = make_ulonglong2(hh[4], hh[5]);
    hp[3] = make_ulonglong2(hh[6], hh[7]);
}

// ---------------------------------------------------------------------------
// Kernel B: out = sigmoid(h @ W2 + b2). W2 register-resident.
// 224 threads/block; thread t<196 owns output cols [4t, 4t+3].
// Each block handles ROWS_PER_BLOCK consecutive rows.
// ---------------------------------------------------------------------------
#define ROWS_PER_BLOCK 128

__global__ void __launch_bounds__(224, 4) qd_gemm_kernel(
    const float* __restrict__ W2, const float* __restrict__ b2,
    float* __restrict__ out)
{
    int t = threadIdx.x;
    if (t >= 196) return;

    // W2 slice -> 16 packed f32x2 registers
    unsigned long long w[8][2];
    const float4* W2v = (const float4*)W2;   // [8][196] float4 view
#pragma unroll
    for (int k = 0; k < 8; k++) {
        float4 wv = W2v[k * 196 + t];
        w[k][0] = pack2(wv.x, wv.y);
        w[k][1] = pack2(wv.z, wv.w);
    }
    float4 bv = ((const float4*)b2)[t];
    const unsigned long long bb0 = pack2(bv.x, bv.y);
    const unsigned long long bb1 = pack2(bv.z, bv.w);

    int r0 = blockIdx.x * ROWS_PER_BLOCK;
    const ulonglong2* hp = ((const ulonglong2*)g_h2) + (size_t)r0 * 4;
    float* outp = out + (size_t)r0 * 784 + 4 * t;

#pragma unroll 2
    for (int rr = 0; rr < ROWS_PER_BLOCK; rr++) {
        ulonglong2 h01 = __ldg(hp + (size_t)rr * 4 + 0);
        ulonglong2 h23 = __ldg(hp + (size_t)rr * 4 + 1);
        ulonglong2 h45 = __ldg(hp + (size_t)rr * 4 + 2);
        ulonglong2 h67 = __ldg(hp + (size_t)rr * 4 + 3);

        unsigned long long a0 = bb0, a1 = bb1;
        a0 = ffma2(h01.x, w[0][0], a0);  a1 = ffma2(h01.x, w[0][1], a1);
        a0 = ffma2(h01.y, w[1][0], a0);  a1 = ffma2(h01.y, w[1][1], a1);
        a0 = ffma2(h23.x, w[2][0], a0);  a1 = ffma2(h23.x, w[2][1], a1);
        a0 = ffma2(h23.y, w[3][0], a0);  a1 = ffma2(h23.y, w[3][1], a1);
        a0 = ffma2(h45.x, w[4][0], a0);  a1 = ffma2(h45.x, w[4][1], a1);
        a0 = ffma2(h45.y, w[5][0], a0);  a1 = ffma2(h45.y, w[5][1], a1);
        a0 = ffma2(h67.x, w[6][0], a0);  a1 = ffma2(h67.x, w[6][1], a1);
        a0 = ffma2(h67.y, w[7][0], a0);  a1 = ffma2(h67.y, w[7][1], a1);

        float f0, f1, f2, f3;
        unpack2(a0, f0, f1);
        unpack2(a1, f2, f3);
        *(float4*)(outp + (size_t)rr * 784) =
            make_float4(sigmoidf_fast(f0), sigmoidf_fast(f1),
                        sigmoidf_fast(f2), sigmoidf_fast(f3));
    }
}

// ---------------------------------------------------------------------------
extern "C" void kernel_launch(void* const* d_in, const int* in_sizes, int n_in,
                              void* d_out, int out_size) {
    const float* z     = (const float*)d_in[0];
    const float* W_in  = (const float*)d_in[1];
    const float* b_in  = (const float*)d_in[2];
    const float* theta = (const float*)d_in[3];
    const float* W1    = (const float*)d_in[4];
    const float* b1    = (const float*)d_in[5];
    const float* W2    = (const float*)d_in[6];
    const float* b2    = (const float*)d_in[7];

    int B = in_sizes[0] / 128;          // 65536
    qd_setup_kernel<<<1, 128>>>(theta);
    qd_front_kernel<<<B / 256, 256>>>(z, W_in, b_in, W1, b1);
    qd_gemm_kernel<<<B / ROWS_PER_BLOCK, 224>>>(W2, b2, (float*)d_out);
}

// round 6
// speedup vs baseline: 2.1865x; 1.5740x over previous
#include <cuda_runtime.h>

// ---------------------------------------------------------------------------
// QuantumDecoder: z -> tanh(z@W_in) -> 4-qubit circuit Z-expectations ->
//                 relu(@W1) -> sigmoid(@W2)
//
// The post-RY circuit (RX/RY/RZ with fixed theta + CX ring, 2 layers) is a
// fixed 16x16 unitary M. With real product state s0 from the RY layer:
//   z_q = s0^T * Re(M^H Z_q M) * s0  =  sum_{i<=j} S_q[i,j] s_i s_j,
//   S_q[i,j] = (i==j ? 1 : 2) * Re(M^H Z_q M)[i,j].
//
// R5: two kernels only.
//  K1 (front): per-block fused sim of the 16 basis columns (threads 0-15,
//     ~1us chain, overlapped across blocks) -> S table in smem; then 1
//     thread/row: z@W_in -> tanh -> s0 -> quadratic forms -> relu layer ->
//     duplicated-f32x2 h to scratch. 512 blocks x 128.
//  K2 (gemm): W2 register-resident (thread owns 4 cols), h staged to smem
//     once per block, broadcast LDS in loop, coalesced float4 stores.
//     16 rows/block, 4096 blocks (fine-grain tail).
// ---------------------------------------------------------------------------

__device__ unsigned long long g_h2[65536 * 8];         // h duplicated as f32x2

// ---- packed f32x2 helpers (Blackwell) -------------------------------------
__device__ __forceinline__ unsigned long long pack2(float x, float y) {
    unsigned long long r;
    asm("mov.b64 %0, {%1, %2};" : "=l"(r) : "f"(x), "f"(y));
    return r;
}
__device__ __forceinline__ void unpack2(unsigned long long v, float& x, float& y) {
    asm("mov.b64 {%0, %1}, %2;" : "=f"(x), "=f"(y) : "l"(v));
}
__device__ __forceinline__ unsigned long long ffma2(unsigned long long a,
                                                    unsigned long long b,
                                                    unsigned long long c) {
    unsigned long long d;
    asm("fma.rn.f32x2 %0, %1, %2, %3;" : "=l"(d) : "l"(a), "l"(b), "l"(c));
    return d;
}
__device__ __forceinline__ float sigmoidf_fast(float x) {
    float e = __expf(-x);                 // MUFU.EX2 path
    return __fdividef(1.0f, 1.0f + e);    // MUFU.RCP path
}

// ---------------------------------------------------------------------------
// K1: front-end with fused per-block setup.
// ---------------------------------------------------------------------------
__global__ void __launch_bounds__(128, 6) qd_front_kernel(
    const float* __restrict__ z,   const float* __restrict__ W_in,
    const float* __restrict__ b_in, const float* __restrict__ theta,
    const float* __restrict__ W1,  const float* __restrict__ b1)
{
    __shared__ float4 sWin[128];        // W_in [128][4]
    __shared__ float2 sM[16][16];       // sM[x][j] = <x| fixed-circuit |j>
    __shared__ float4 sS4[136];         // symmetric pair coeffs (4 q's each)
    __shared__ float  sW1[32];          // W1 [4][8]
    __shared__ float  sb1[8];
    __shared__ float  sbin[4];

    int tid = threadIdx.x;
    sWin[tid] = ((const float4*)W_in)[tid];
    if (tid < 32) sW1[tid] = W1[tid];
    if (tid < 8)  sb1[tid] = b1[tid];
    if (tid < 4)  sbin[tid] = b_in[tid];

    // ---- per-block sim of the fixed circuit on basis state |tid> ----------
    if (tid < 16) {
        float2 st[16];
#pragma unroll
        for (int x = 0; x < 16; x++) st[x] = make_float2(0.f, 0.f);
        st[tid] = make_float2(1.f, 0.f);

#pragma unroll
        for (int layer = 0; layer < 2; layer++) {
#pragma unroll
            for (int q = 0; q < 4; q++) {
                float th = theta[layer * 4 + q];
                float ch, sh;
                __sincosf(0.5f * th, &sh, &ch);
                int bit = 1 << q;
#pragma unroll
                for (int a = 0; a < 8; a++) {
                    int i0 = ((a >> q) << (q + 1)) | (a & (bit - 1));
                    int i1 = i0 | bit;
                    float2 x0 = st[i0], x1 = st[i1];
                    // Rx = [[c, -i s], [-i s, c]]
                    float2 y0 = make_float2(ch * x0.x + sh * x1.y, ch * x0.y - sh * x1.x);
                    float2 y1 = make_float2(ch * x1.x + sh * x0.y, ch * x1.y - sh * x0.x);
                    // Ry = [[c, -s], [s, c]]
                    float2 z0 = make_float2(ch * y0.x - sh * y1.x, ch * y0.y - sh * y1.y);
                    float2 z1 = make_float2(sh * y0.x + ch * y1.x, sh * y0.y + ch * y1.y);
                    // Rz = diag(c - i s, c + i s)
                    st[i0] = make_float2(ch * z0.x + sh * z0.y, ch * z0.y - sh * z0.x);
                    st[i1] = make_float2(ch * z1.x - sh * z1.y, ch * z1.y + sh * z1.x);
                }
            }
            // CX ring: (c,t) = (0,1),(1,2),(2,3),(3,0)
            const int cs[4] = {0, 1, 2, 3};
            const int ts[4] = {1, 2, 3, 0};
#pragma unroll
            for (int g = 0; g < 4; g++) {
                float2 tmp[16];
                int c = cs[g], t = ts[g];
#pragma unroll
                for (int m = 0; m < 16; m++) tmp[m] = st[m ^ (((m >> c) & 1) << t)];
#pragma unroll
                for (int m = 0; m < 16; m++) st[m] = tmp[m];
            }
        }
#pragma unroll
        for (int x = 0; x < 16; x++) sM[x][tid] = st[x];
    }
    __syncthreads();

    // ---- S table: 544 entries, direct from sM -----------------------------
    for (int e = tid; e < 544; e += 128) {
        int pair = e >> 2, q = e & 3;
        int i = 0, rem = pair;
        while (rem >= 16 - i) { rem -= 16 - i; i++; }
        int j = i + rem;
        float s = 0.f;
#pragma unroll
        for (int x = 0; x < 16; x++) {
            float2 mi = sM[x][i], mj = sM[x][j];
            float d = mi.x * mj.x + mi.y * mj.y;   // Re(conj(M[x,i])*M[x,j])
            s += ((x >> q) & 1) ? -d : d;
        }
        ((float*)sS4)[pair * 4 + q] = (i == j ? 1.f : 2.f) * s;
    }
    __syncthreads();

    int r = blockIdx.x * 128 + tid;

    // ---- 1) lat = tanh(z_row @ W_in + b_in) -------------------------------
    const float4* zp = (const float4*)(z + (size_t)r * 128);
    float ax = sbin[0], ay = sbin[1], az = sbin[2], aw = sbin[3];
#pragma unroll 8
    for (int k = 0; k < 32; k++) {
        float4 zv = zp[k];
        float4 wa = sWin[4 * k + 0], wb = sWin[4 * k + 1];
        float4 wc = sWin[4 * k + 2], wd = sWin[4 * k + 3];
        ax = fmaf(zv.x, wa.x, ax); ay = fmaf(zv.x, wa.y, ay);
        az = fmaf(zv.x, wa.z, az); aw = fmaf(zv.x, wa.w, aw);
        ax = fmaf(zv.y, wb.x, ax); ay = fmaf(zv.y, wb.y, ay);
        az = fmaf(zv.y, wb.z, az); aw = fmaf(zv.y, wb.w, aw);
        ax = fmaf(zv.z, wc.x, ax); ay = fmaf(zv.z, wc.y, ay);
        az = fmaf(zv.z, wc.z, az); aw = fmaf(zv.z, wc.w, aw);
        ax = fmaf(zv.w, wd.x, ax); ay = fmaf(zv.w, wd.y, ay);
        az = fmaf(zv.w, wd.z, az); aw = fmaf(zv.w, wd.w, aw);
    }
    float a0 = tanhf(ax), a1 = tanhf(ay), a2 = tanhf(az), a3 = tanhf(aw);

    // ---- 2) s0: real RY product state -------------------------------------
    float c0, s0s, c1, s1s, c2, s2s, c3, s3s;
    __sincosf(0.5f * a0, &s0s, &c0);
    __sincosf(0.5f * a1, &s1s, &c1);
    __sincosf(0.5f * a2, &s2s, &c2);
    __sincosf(0.5f * a3, &s3s, &c3);
    float u0 = c0 * c1, u1 = s0s * c1, u2 = c0 * s1s, u3 = s0s * s1s;
    float v0 = c2 * c3, v1 = s2s * c3, v2 = c2 * s3s, v3 = s2s * s3s;
    float st[16];
    st[0]  = u0 * v0; st[1]  = u1 * v0; st[2]  = u2 * v0; st[3]  = u3 * v0;
    st[4]  = u0 * v1; st[5]  = u1 * v1; st[6]  = u2 * v1; st[7]  = u3 * v1;
    st[8]  = u0 * v2; st[9]  = u1 * v2; st[10] = u2 * v2; st[11] = u3 * v2;
    st[12] = u0 * v3; st[13] = u1 * v3; st[14] = u2 * v3; st[15] = u3 * v3;

    // ---- 3) all 4 quadratic forms via symmetric pair table ----------------
    float zq0 = 0.f, zq1 = 0.f, zq2 = 0.f, zq3 = 0.f;
    {
        int pidx = 0;
#pragma unroll
        for (int i = 0; i < 16; i++) {
            float si = st[i];
#pragma unroll
            for (int j = i; j < 16; j++) {
                float p = si * st[j];
                float4 cv = sS4[pidx++];
                zq0 = fmaf(p, cv.x, zq0);
                zq1 = fmaf(p, cv.y, zq1);
                zq2 = fmaf(p, cv.z, zq2);
                zq3 = fmaf(p, cv.w, zq3);
            }
        }
    }

    // ---- 4) h = relu(qexp @ W1 + b1);  qexp[k] = zq[3-k]; store dup'd -----
    unsigned long long hh[8];
#pragma unroll
    for (int m = 0; m < 8; m++) {
        float t = sb1[m];
        t = fmaf(zq3, sW1[0 * 8 + m], t);
        t = fmaf(zq2, sW1[1 * 8 + m], t);
        t = fmaf(zq1, sW1[2 * 8 + m], t);
        t = fmaf(zq0, sW1[3 * 8 + m], t);
        t = fmaxf(t, 0.f);
        hh[m] = pack2(t, t);
    }
    ulonglong2* hp = (ulonglong2*)(g_h2 + (size_t)r * 8);
    hp[0] = make_ulonglong2(hh[0], hh[1]);
    hp[1] = make_ulonglong2(hh[2], hh[3]);
    hp[2] = make_ulonglong2(hh[4], hh[5]);
    hp[3] = make_ulonglong2(hh[6], hh[7]);
}

// ---------------------------------------------------------------------------
// K2: out = sigmoid(h @ W2 + b2). W2 register-resident; h staged in smem.
// 224 threads/block; thread t<196 owns output cols [4t, 4t+3].
// ---------------------------------------------------------------------------
#define ROWS_PER_BLOCK 16

__global__ void __launch_bounds__(224, 4) qd_gemm_kernel(
    const float* __restrict__ W2, const float* __restrict__ b2,
    float* __restrict__ out)
{
    __shared__ ulonglong2 sh[ROWS_PER_BLOCK * 4];    // 16 rows x 4x(f32x2 pair)

    int t = threadIdx.x;
    int r0 = blockIdx.x * ROWS_PER_BLOCK;

    // stage this block's h rows (1 KB, coalesced)
    if (t < ROWS_PER_BLOCK * 4)
        sh[t] = ((const ulonglong2*)g_h2)[(size_t)r0 * 4 + t];

    // W2 slice -> 16 packed f32x2 registers
    unsigned long long w[8][2];
    unsigned long long bb0 = 0, bb1 = 0;
    if (t < 196) {
        const float4* W2v = (const float4*)W2;   // [8][196] float4 view
#pragma unroll
        for (int k = 0; k < 8; k++) {
            float4 wv = W2v[k * 196 + t];
            w[k][0] = pack2(wv.x, wv.y);
            w[k][1] = pack2(wv.z, wv.w);
        }
        float4 bv = ((const float4*)b2)[t];
        bb0 = pack2(bv.x, bv.y);
        bb1 = pack2(bv.z, bv.w);
    }
    __syncthreads();
    if (t >= 196) return;

    float* outp = out + (size_t)r0 * 784 + 4 * t;

#pragma unroll 4
    for (int rr = 0; rr < ROWS_PER_BLOCK; rr++) {
        ulonglong2 h01 = sh[rr * 4 + 0];
        ulonglong2 h23 = sh[rr * 4 + 1];
        ulonglong2 h45 = sh[rr * 4 + 2];
        ulonglong2 h67 = sh[rr * 4 + 3];

        unsigned long long a0 = bb0, a1 = bb1;
        a0 = ffma2(h01.x, w[0][0], a0);  a1 = ffma2(h01.x, w[0][1], a1);
        a0 = ffma2(h01.y, w[1][0], a0);  a1 = ffma2(h01.y, w[1][1], a1);
        a0 = ffma2(h23.x, w[2][0], a0);  a1 = ffma2(h23.x, w[2][1], a1);
        a0 = ffma2(h23.y, w[3][0], a0);  a1 = ffma2(h23.y, w[3][1], a1);
        a0 = ffma2(h45.x, w[4][0], a0);  a1 = ffma2(h45.x, w[4][1], a1);
        a0 = ffma2(h45.y, w[5][0], a0);  a1 = ffma2(h45.y, w[5][1], a1);
        a0 = ffma2(h67.x, w[6][0], a0);  a1 = ffma2(h67.x, w[6][1], a1);
        a0 = ffma2(h67.y, w[7][0], a0);  a1 = ffma2(h67.y, w[7][1], a1);

        float f0, f1, f2, f3;
        unpack2(a0, f0, f1);
        unpack2(a1, f2, f3);
        *(float4*)(outp + (size_t)rr * 784) =
            make_float4(sigmoidf_fast(f0), sigmoidf_fast(f1),
                        sigmoidf_fast(f2), sigmoidf_fast(f3));
    }
}

// ---------------------------------------------------------------------------
extern "C" void kernel_launch(void* const* d_in, const int* in_sizes, int n_in,
                              void* d_out, int out_size) {
    const float* z     = (const float*)d_in[0];
    const float* W_in  = (const float*)d_in[1];
    const float* b_in  = (const float*)d_in[2];
    const float* theta = (const float*)d_in[3];
    const float* W1    = (const float*)d_in[4];
    const float* b1    = (const float*)d_in[5];
    const float* W2    = (const float*)d_in[6];
    const float* b2    = (const float*)d_in[7];

    int B = in_sizes[0] / 128;          // 65536
    qd_front_kernel<<<B / 128, 128>>>(z, W_in, b_in, theta, W1, b1);
    qd_gemm_kernel<<<B / ROWS_PER_BLOCK, 224>>>(W2, b2, (float*)d_out);
}